// round 8
// baseline (speedup 1.0000x reference)
#include <cuda_runtime.h>
#include <cuda_bf16.h>
#include <math.h>
#include <cstdint>

#define Bsz 4
#define Tsz 2048
#define DMx 1024
#define Hh  16
#define Dd  64
#define INNERx 1024
#define ROWS (Bsz*Tsz)   // 8192
#define CH 64
#define NCH (Tsz/CH)     // 32
#define BH (Bsz*Hh)      // 64
#define KDIM 1024
#define NCH2 24          // 3*KDIM/128 (3-term split, K-chunk 128)

typedef unsigned long long ull;
typedef __nv_bfloat16 bf16;

// ---------------- scratch ----------------
__device__ float g_Q[ROWS*INNERx];
__device__ float g_K[ROWS*INNERx];
__device__ float g_V[ROWS*INNERx];
__device__ float g_Y[ROWS*INNERx];
__device__ float g_alpha[ROWS*Hh];
__device__ float g_beta[ROWS*Hh];
__device__ float g_U[BH*NCH*Dd*Dd];
__device__ float g_Sc[BH*NCH*Dd*Dd];
__device__ float g_G[BH*NCH];
__device__ float g_gt[BH*Tsz];
__device__ bf16 g_xh[ROWS*DMx];
__device__ bf16 g_xl[ROWS*DMx];
__device__ bf16 g_yh[ROWS*INNERx];
__device__ bf16 g_yl[ROWS*INNERx];
__device__ bf16 g_wqh[DMx*INNERx], g_wql[DMx*INNERx];
__device__ bf16 g_wkh[DMx*INNERx], g_wkl[DMx*INNERx];
__device__ bf16 g_wvh[DMx*INNERx], g_wvl[DMx*INNERx];
__device__ bf16 g_woh[INNERx*DMx], g_wol[INNERx*DMx];

// ---------------- helpers ----------------
__device__ __forceinline__ uint32_t smem_to_u32(const void* p){
    uint32_t a;
    asm("{ .reg .u64 t; cvta.to.shared.u64 t, %1; cvt.u32.u64 %0, t; }" : "=r"(a) : "l"(p));
    return a;
}
__device__ __forceinline__ void cp_async16(uint32_t dst, const void* src){
    asm volatile("cp.async.cg.shared.global [%0], [%1], 16;" :: "r"(dst), "l"(src));
}
#define CP_COMMIT() asm volatile("cp.async.commit_group;" ::: "memory")
#define CP_WAIT(n)  asm volatile("cp.async.wait_group %0;" :: "n"(n) : "memory")

__device__ __forceinline__ void ldsm_x4(uint32_t* r, uint32_t addr){
    asm volatile("ldmatrix.sync.aligned.m8n8.x4.shared.b16 {%0,%1,%2,%3}, [%4];"
        : "=r"(r[0]), "=r"(r[1]), "=r"(r[2]), "=r"(r[3]) : "r"(addr));
}
__device__ __forceinline__ void mma_bf16(float* c, const uint32_t* a, const uint32_t* b){
    asm volatile(
        "mma.sync.aligned.m16n8k16.row.col.f32.bf16.bf16.f32 "
        "{%0,%1,%2,%3}, {%4,%5,%6,%7}, {%8,%9}, {%0,%1,%2,%3};"
        : "+f"(c[0]), "+f"(c[1]), "+f"(c[2]), "+f"(c[3])
        : "r"(a[0]), "r"(a[1]), "r"(a[2]), "r"(a[3]), "r"(b[0]), "r"(b[1]));
}
__device__ __forceinline__ ull pack_dup(float a){
    ull r; unsigned int u = __float_as_uint(a);
    asm("mov.b64 %0, {%1, %1};" : "=l"(r) : "r"(u));
    return r;
}
__device__ __forceinline__ void ffma2(ull& d, ull a, ull b){
    asm("fma.rn.f32x2 %0, %1, %2, %3;" : "=l"(d) : "l"(a), "l"(b), "l"(d));
}
__device__ __forceinline__ float lo_of(ull v){ return __uint_as_float((unsigned)(v & 0xffffffffull)); }
__device__ __forceinline__ float hi_of(ull v){ return __uint_as_float((unsigned)(v >> 32)); }

// ---------------- conversion kernels ----------------
__global__ __launch_bounds__(256)
void conv_split(const float* __restrict__ src, bf16* __restrict__ h,
                bf16* __restrict__ l){
    const size_t i = (size_t)blockIdx.x * 256 + threadIdx.x;
    float4 v = *(const float4*)(src + i * 4);
    bf16 h0 = __float2bfloat16(v.x), h1 = __float2bfloat16(v.y);
    bf16 h2 = __float2bfloat16(v.z), h3 = __float2bfloat16(v.w);
    bf16 l0 = __float2bfloat16(v.x - __bfloat162float(h0));
    bf16 l1 = __float2bfloat16(v.y - __bfloat162float(h1));
    bf16 l2 = __float2bfloat16(v.z - __bfloat162float(h2));
    bf16 l3 = __float2bfloat16(v.w - __bfloat162float(h3));
    __nv_bfloat162* hp = (__nv_bfloat162*)(h + i * 4);
    __nv_bfloat162* lp = (__nv_bfloat162*)(l + i * 4);
    hp[0] = __nv_bfloat162{h0, h1}; hp[1] = __nv_bfloat162{h2, h3};
    lp[0] = __nv_bfloat162{l0, l1}; lp[1] = __nv_bfloat162{l2, l3};
}

// all 4 weight transposes in one launch: z selects {Wq,Wk,Wv,Wo}
__global__ __launch_bounds__(256)
void trans_split_all(const float* __restrict__ W0, const float* __restrict__ W1,
                     const float* __restrict__ W2, const float* __restrict__ W3){
    __shared__ float ts[32][33];
    const int z = blockIdx.z;
    const float* W = (z == 0) ? W0 : (z == 1) ? W1 : (z == 2) ? W2 : W3;
    bf16* Th = (z == 0) ? g_wqh : (z == 1) ? g_wkh : (z == 2) ? g_wvh : g_woh;
    bf16* Tl = (z == 0) ? g_wql : (z == 1) ? g_wkl : (z == 2) ? g_wvl : g_wol;
    const int k0 = blockIdx.y * 32, n0 = blockIdx.x * 32;
    const int tx = threadIdx.x & 31, ty = threadIdx.x >> 5;
    for (int i = ty; i < 32; i += 8)
        ts[i][tx] = W[(size_t)(k0 + i) * 1024 + n0 + tx];
    __syncthreads();
    for (int i = ty; i < 32; i += 8){
        float v = ts[tx][i];
        bf16 h = __float2bfloat16(v);
        bf16 l = __float2bfloat16(v - __bfloat162float(h));
        Th[(size_t)(n0 + i) * 1024 + k0 + tx] = h;
        Tl[(size_t)(n0 + i) * 1024 + k0 + tx] = l;
    }
}

// ---------------- bf16-split mma.sync GEMM core --------------------------------
// 128x256 CTA tile, 8 warps (2x4) of 64x64, K-chunk 128 (two 128B sub-blocks),
// 2-stage cp.async (96KB/stage), fragment double-buffering across ks-steps.
// Extended K = 3072 via 3 phases; 24 chunks total.
#define STAGE_BYTES 98304      // A 32KB (2 halves) + B 64KB (2 halves)
#define GEMM_SMEM   (2*STAGE_BYTES)

__device__ __forceinline__ void gemm_core(
    const bf16* __restrict__ Ah, const bf16* __restrict__ Al,
    const bf16* __restrict__ Bh, const bf16* __restrict__ Bl,
    float* __restrict__ C, int N, int bm, int bn)
{
    extern __shared__ __align__(128) char sm[];
    const uint32_t sb = smem_to_u32(sm);
    const int tid = threadIdx.x, lane = tid & 31, wid = tid >> 5;  // 8 warps
    const int wm = wid >> 2, wn = wid & 3;                          // 2x4, 64x64 tiles

    float acc[4][8][4];
    #pragma unroll
    for (int mt = 0; mt < 4; mt++)
        #pragma unroll
        for (int nt = 0; nt < 8; nt++)
            #pragma unroll
            for (int e = 0; e < 4; e++) acc[mt][nt][e] = 0.f;

    // cp.async mapping: 256 threads; per row 256B = 2 halves x 8 16B-units
    const int arow_base = tid >> 4;          // 0..15
    const int half = (tid >> 3) & 1;         // k-half
    const int useg = tid & 7;                // 16B unit within half
    const int kadd = half * 64 + useg * 8;   // element offset within 128-k chunk
    const int bo0 = useg * 16;

    auto issue_stage = [&](int buf, int c){
        const int p = c >> 3, kk0 = (c & 7) << 7;
        const bf16* As = (p == 1) ? Al : Ah;
        const bf16* Bs = (p == 2) ? Bl : Bh;
        const uint32_t abase = sb + buf * STAGE_BYTES + half * 16384;
        const uint32_t bbase = sb + buf * STAGE_BYTES + 32768 + half * 32768;
        #pragma unroll
        for (int i = 0; i < 8; i++){
            const int row = arow_base + i * 16;
            const int bo = row * 128 + bo0;
            cp_async16(abase + (bo ^ ((bo >> 3) & 0x70)),
                       As + (size_t)(bm + row) * KDIM + kk0 + kadd);
        }
        #pragma unroll
        for (int i = 0; i < 16; i++){
            const int row = arow_base + i * 16;
            const int bo = row * 128 + bo0;
            cp_async16(bbase + (bo ^ ((bo >> 3) & 0x70)),
                       Bs + (size_t)(bn + row) * KDIM + kk0 + kadd);
        }
    };

    auto load_afr = [&](uint32_t stbase, int ks, uint32_t (*afr)[4]){
        const uint32_t ab = stbase + (ks >> 2) * 16384;
        const int ksl = ks & 3;
        #pragma unroll
        for (int mt = 0; mt < 4; mt++){
            const int row = wm * 64 + mt * 16 + (lane & 15);
            const int bo = row * 128 + ksl * 32 + ((lane >> 4) << 4);
            ldsm_x4(afr[mt], ab + (bo ^ ((bo >> 3) & 0x70)));
        }
    };
    auto load_bfr = [&](uint32_t stbase, int ks, uint32_t (*bfr)[4]){
        const uint32_t bb = stbase + 32768 + (ks >> 2) * 32768;
        const int ksl = ks & 3;
        const int g = lane >> 3;
        #pragma unroll
        for (int np = 0; np < 4; np++){
            const int row = wn * 64 + np * 16 + ((g >> 1) << 3) + (lane & 7);
            const int bo = row * 128 + ksl * 32 + ((g & 1) << 4);
            ldsm_x4(bfr[np], bb + (bo ^ ((bo >> 3) & 0x70)));
        }
    };

    issue_stage(0, 0); CP_COMMIT();
    int buf = 0;
    uint32_t afr[2][4][4], bfr[2][4][4];
    for (int c = 0; c < NCH2; c++){
        CP_WAIT(0);
        __syncthreads();
        if (c + 1 < NCH2){ issue_stage(buf ^ 1, c + 1); CP_COMMIT(); }
        const uint32_t stbase = sb + buf * STAGE_BYTES;
        load_afr(stbase, 0, afr[0]);
        load_bfr(stbase, 0, bfr[0]);
        #pragma unroll
        for (int ks = 0; ks < 8; ks++){
            const int cur = ks & 1, nxt = cur ^ 1;
            if (ks < 7){
                load_afr(stbase, ks + 1, afr[nxt]);
                load_bfr(stbase, ks + 1, bfr[nxt]);
            }
            #pragma unroll
            for (int mt = 0; mt < 4; mt++)
                #pragma unroll
                for (int nt = 0; nt < 8; nt++)
                    mma_bf16(acc[mt][nt], afr[cur][mt], &bfr[cur][nt >> 1][(nt & 1) * 2]);
        }
        buf ^= 1;
    }

    const int r0 = lane >> 2, cb = (lane & 3) << 1;
    #pragma unroll
    for (int mt = 0; mt < 4; mt++){
        const int grow = bm + wm * 64 + mt * 16 + r0;
        #pragma unroll
        for (int nt = 0; nt < 8; nt++){
            const int gcol = bn + wn * 64 + nt * 8 + cb;
            *(float2*)(C + (size_t)grow * N + gcol) =
                make_float2(acc[mt][nt][0], acc[mt][nt][1]);
            *(float2*)(C + (size_t)(grow + 8) * N + gcol) =
                make_float2(acc[mt][nt][2], acc[mt][nt][3]);
        }
    }
}

// fused Q/K/V projection: grid (12, 64); column tile selects weight + output
__global__ __launch_bounds__(256, 1)
void gemm_qkv(const bf16* __restrict__ Ah, const bf16* __restrict__ Al,
              float* __restrict__ Q, float* __restrict__ K, float* __restrict__ V){
    const int sel = blockIdx.x >> 2;
    const int bn = (blockIdx.x & 3) * 256;
    const int bm = blockIdx.y * 128;
    const bf16* Bh = (sel == 0) ? g_wqh : (sel == 1) ? g_wkh : g_wvh;
    const bf16* Bl = (sel == 0) ? g_wql : (sel == 1) ? g_wkl : g_wvl;
    float* C = (sel == 0) ? Q : (sel == 1) ? K : V;
    gemm_core(Ah, Al, Bh, Bl, C, INNERx, bm, bn);
}

__global__ __launch_bounds__(256, 1)
void gemm_out(const bf16* __restrict__ Ah, const bf16* __restrict__ Al,
              float* __restrict__ C){
    gemm_core(Ah, Al, g_woh, g_wol, C, DMx, blockIdx.y * 128, blockIdx.x * 256);
}

// ---------------- alpha/beta gate GEMM ----------------
__global__ __launch_bounds__(256)
void ab_kernel(const float* __restrict__ x,
               const float* __restrict__ Wa, const float* __restrict__ ba,
               const float* __restrict__ Wb, const float* __restrict__ bb,
               float* __restrict__ alpha, float* __restrict__ beta){
    __shared__ float xs[32][40];
    __shared__ float Ws[32][32];
    const int tid = threadIdx.x;
    const int r = tid >> 3, sub = tid & 7;
    const int row0 = blockIdx.x * 32;
    ull acc[2] = {0ull, 0ull};
    for (int k0 = 0; k0 < DMx; k0 += 32){
        #pragma unroll
        for (int q = 0; q < 4; q++){
            int idx = tid + q * 256;
            int kk = idx >> 5, cc = idx & 31;
            Ws[kk][cc] = (cc < 16) ? Wa[(size_t)(k0 + kk) * Hh + cc]
                                   : Wb[(size_t)(k0 + kk) * Hh + cc - 16];
        }
        {
            const int rr = tid >> 3, seg = tid & 7;
            float4 v = *(const float4*)(x + (size_t)(row0 + rr) * DMx + k0 + seg * 4);
            *(float4*)&xs[rr][seg * 4] = v;
        }
        __syncthreads();
        #pragma unroll
        for (int kk = 0; kk < 32; kk++){
            ull xv = pack_dup(xs[r][kk]);
            const ull* wp = (const ull*)&Ws[kk][sub * 4];
            ffma2(acc[0], xv, wp[0]);
            ffma2(acc[1], xv, wp[1]);
        }
        __syncthreads();
    }
    #pragma unroll
    for (int j = 0; j < 2; j++){
        float lo = lo_of(acc[j]), hi = hi_of(acc[j]);
        #pragma unroll
        for (int p = 0; p < 2; p++){
            float v = p ? hi : lo;
            int cc = sub * 4 + j * 2 + p;
            float bias = (cc < 16) ? ba[cc] : bb[cc - 16];
            float sig = 1.f / (1.f + expf(-(v + bias)));
            if (cc < 16) alpha[(size_t)(row0 + r) * Hh + cc] = sig;
            else         beta [(size_t)(row0 + r) * Hh + cc - 16] = sig;
        }
    }
}

// ---------------- K1: intra-chunk attention + chunk summary --------------------
#define TP 66
#define INTRA_SMEM ((3*64*TP + 192) * 4)

__global__ __launch_bounds__(256)
void chunk_intra(const float* __restrict__ Q, const float* __restrict__ K,
                 const float* __restrict__ V,
                 const float* __restrict__ alpha, const float* __restrict__ beta,
                 float* __restrict__ Yout, float* __restrict__ U,
                 float* __restrict__ Gout, float* __restrict__ gt_out){
    extern __shared__ float smf[];
    float* Qs  = smf;
    float* Ks  = smf + 64*TP;
    float* Vs  = smf + 2*64*TP;
    float* slg = smf + 3*64*TP;
    float* sb  = slg + 64;
    float* sw  = sb + 64;

    const int c  = blockIdx.x;
    const int bh = blockIdx.y;
    const int b  = bh >> 4, h = bh & 15;
    const int tid = threadIdx.x;
    const size_t base = ((size_t)(b * Tsz + c * CH) * Hh + h) * Dd;

    {
        const int r = tid >> 2, quad = tid & 3;
        const size_t off = base + (size_t)r * INNERx + quad * 16;
        float4 q0 = *(const float4*)(Q + off),     q1 = *(const float4*)(Q + off + 4);
        float4 q2 = *(const float4*)(Q + off + 8), q3 = *(const float4*)(Q + off + 12);
        float4 k0 = *(const float4*)(K + off),     k1 = *(const float4*)(K + off + 4);
        float4 k2 = *(const float4*)(K + off + 8), k3 = *(const float4*)(K + off + 12);
        float4 v0 = *(const float4*)(V + off),     v1 = *(const float4*)(V + off + 4);
        float4 v2 = *(const float4*)(V + off + 8), v3 = *(const float4*)(V + off + 12);
        float ss = k0.x*k0.x + k0.y*k0.y + k0.z*k0.z + k0.w*k0.w
                 + k1.x*k1.x + k1.y*k1.y + k1.z*k1.z + k1.w*k1.w
                 + k2.x*k2.x + k2.y*k2.y + k2.z*k2.z + k2.w*k2.w
                 + k3.x*k3.x + k3.y*k3.y + k3.z*k3.z + k3.w*k3.w;
        ss += __shfl_xor_sync(0xffffffffu, ss, 1);
        ss += __shfl_xor_sync(0xffffffffu, ss, 2);
        float inv = 1.f / fmaxf(sqrtf(ss), 1e-12f);
        float* qr = Qs + r * TP + quad * 16;
        float* kr = Ks + r * TP + quad * 16;
        float* vr = Vs + r * TP + quad * 16;
        qr[0]=q0.x; qr[1]=q0.y; qr[2]=q0.z; qr[3]=q0.w;
        qr[4]=q1.x; qr[5]=q1.y; qr[6]=q1.z; qr[7]=q1.w;
        qr[8]=q2.x; qr[9]=q2.y; qr[10]=q2.z; qr[11]=q2.w;
        qr[12]=q3.x; qr[13]=q3.y; qr[14]=q3.z; qr[15]=q3.w;
        kr[0]=k0.x*inv; kr[1]=k0.y*inv; kr[2]=k0.z*inv; kr[3]=k0.w*inv;
        kr[4]=k1.x*inv; kr[5]=k1.y*inv; kr[6]=k1.z*inv; kr[7]=k1.w*inv;
        kr[8]=k2.x*inv; kr[9]=k2.y*inv; kr[10]=k2.z*inv; kr[11]=k2.w*inv;
        kr[12]=k3.x*inv; kr[13]=k3.y*inv; kr[14]=k3.z*inv; kr[15]=k3.w*inv;
        vr[0]=v0.x; vr[1]=v0.y; vr[2]=v0.z; vr[3]=v0.w;
        vr[4]=v1.x; vr[5]=v1.y; vr[6]=v1.z; vr[7]=v1.w;
        vr[8]=v2.x; vr[9]=v2.y; vr[10]=v2.z; vr[11]=v2.w;
        vr[12]=v3.x; vr[13]=v3.y; vr[14]=v3.z; vr[15]=v3.w;
    }
    if (tid < 64){
        size_t gidx = (size_t)(b * Tsz + c * CH + tid) * Hh + h;
        slg[tid] = __logf(alpha[gidx]);
        sb[tid]  = beta[gidx];
    }
    __syncthreads();
    if (tid == 0){
        float s = 0.f;
        for (int j = 0; j < CH; j++){ s += slg[j]; slg[j] = s; }
    }
    __syncthreads();
    if (tid < 64){
        float lg_last = slg[63];
        sw[tid] = __expf(lg_last - slg[tid]) * sb[tid];
        float g = __expf(slg[tid]);
        gt_out[(size_t)bh * Tsz + c * CH + tid] = g;
        if (tid == 63) Gout[bh * NCH + c] = g;
    }
    __syncthreads();

    const int tr  = (tid >> 4) << 2;
    const int tc4 = (tid & 15) << 2;

    ull accM2[4][4];
    #pragma unroll
    for (int i=0;i<4;i++)
        #pragma unroll
        for (int j=0;j<4;j++) accM2[i][j] = 0ull;
    #pragma unroll 8
    for (int d = 0; d < Dd; d += 2){
        ull q2[4], k2[4];
        #pragma unroll
        for (int i=0;i<4;i++) q2[i] = *(const ull*)&Qs[(tr+i)*TP + d];
        #pragma unroll
        for (int j=0;j<4;j++) k2[j] = *(const ull*)&Ks[(tc4+j)*TP + d];
        #pragma unroll
        for (int i=0;i<4;i++)
            #pragma unroll
            for (int j=0;j<4;j++) ffma2(accM2[i][j], q2[i], k2[j]);
    }
    __syncthreads();
    #pragma unroll
    for (int i=0;i<4;i++){
        int tau = tr + i;
        float lgt = slg[tau];
        #pragma unroll
        for (int j=0;j<4;j++){
            int jj = tc4 + j;
            float p = 0.f;
            if (tau >= jj)
                p = __expf(lgt - slg[jj]) * sb[jj] * (lo_of(accM2[i][j]) + hi_of(accM2[i][j]));
            Qs[tau*TP + jj] = p;
        }
    }
    __syncthreads();

    ull accY2[4][2], accU2[4][2];
    #pragma unroll
    for (int i=0;i<4;i++){
        accY2[i][0]=0ull; accY2[i][1]=0ull; accU2[i][0]=0ull; accU2[i][1]=0ull;
    }
    #pragma unroll 4
    for (int j = 0; j < CH; j++){
        float wj = sw[j];
        ull vf0 = *(const ull*)&Vs[j*TP + tc4];
        ull vf1 = *(const ull*)&Vs[j*TP + tc4 + 2];
        ull kf0 = *(const ull*)&Ks[j*TP + tc4];
        ull kf1 = *(const ull*)&Ks[j*TP + tc4 + 2];
        #pragma unroll
        for (int i=0;i<4;i++){
            ull pf = pack_dup(Qs[(tr+i)*TP + j]);
            ull vu = pack_dup(Vs[j*TP + tr + i] * wj);
            ffma2(accY2[i][0], pf, vf0);
            ffma2(accY2[i][1], pf, vf1);
            ffma2(accU2[i][0], vu, kf0);
            ffma2(accU2[i][1], vu, kf1);
        }
    }
    #pragma unroll
    for (int i=0;i<4;i++){
        float* yr = Yout + base + (size_t)(tr + i) * INNERx + tc4;
        *(float4*)yr = make_float4(lo_of(accY2[i][0]), hi_of(accY2[i][0]),
                                   lo_of(accY2[i][1]), hi_of(accY2[i][1]));
        float* ur = U + ((size_t)(bh * NCH + c) * 4096) + (tr + i) * 64 + tc4;
        *(float4*)ur = make_float4(lo_of(accU2[i][0]), hi_of(accU2[i][0]),
                                   lo_of(accU2[i][1]), hi_of(accU2[i][1]));
    }
}

// ---------------- K2: chunk-level state scan -----------------------------------
__global__ __launch_bounds__(256)
void chunk_scan(const float* __restrict__ U, const float* __restrict__ G,
                const float* __restrict__ state0,
                float* __restrict__ Sc, float* __restrict__ stateOut){
    const int bh = blockIdx.x;
    const int tid = threadIdx.x;
    float S[16];
    const size_t bs = (size_t)bh * 4096;
    #pragma unroll
    for (int j = 0; j < 16; j++) S[j] = state0[bs + j * 256 + tid];
    for (int c = 0; c < NCH; c++){
        const size_t uc = ((size_t)(bh * NCH + c)) * 4096;
        float g = __ldg(&G[bh * NCH + c]);
        float u[16];
        #pragma unroll
        for (int j = 0; j < 16; j++) u[j] = U[uc + j * 256 + tid];
        #pragma unroll
        for (int j = 0; j < 16; j++){
            Sc[uc + j * 256 + tid] = S[j];
            S[j] = fmaf(g, S[j], u[j]);
        }
    }
    #pragma unroll
    for (int j = 0; j < 16; j++) stateOut[bs + j * 256 + tid] = S[j];
}

// ---------------- K3: Y += diag(g) Q S^T ; emit bf16 hi/lo split of Y ----------
__global__ __launch_bounds__(256)
void chunk_inter(const float* __restrict__ Q, const float* __restrict__ Sc,
                 const float* __restrict__ gt, const float* __restrict__ Y,
                 bf16* __restrict__ Yh, bf16* __restrict__ Yl){
    __shared__ float Qs[64*TP];
    __shared__ float Ss[64*TP];
    __shared__ float sg[64];
    const int c  = blockIdx.x;
    const int bh = blockIdx.y;
    const int b  = bh >> 4, h = bh & 15;
    const int tid = threadIdx.x;
    const size_t base = ((size_t)(b * Tsz + c * CH) * Hh + h) * Dd;
    {
        const int r = tid >> 2, quad = tid & 3;
        const size_t off = base + (size_t)r * INNERx + quad * 16;
        const size_t soff = ((size_t)(bh * NCH + c)) * 4096 + r * 64 + quad * 16;
        #pragma unroll
        for (int l = 0; l < 16; l += 4){
            float4 qv = *(const float4*)(Q + off + l);
            float4 sv = *(const float4*)(Sc + soff + l);
            float* qr = Qs + r * TP + quad * 16 + l;
            float* sr = Ss + r * TP + quad * 16 + l;
            qr[0]=qv.x; qr[1]=qv.y; qr[2]=qv.z; qr[3]=qv.w;
            sr[0]=sv.x; sr[1]=sv.y; sr[2]=sv.z; sr[3]=sv.w;
        }
    }
    if (tid < 64) sg[tid] = gt[(size_t)bh * Tsz + c * CH + tid];
    __syncthreads();
    const int tr  = (tid >> 4) << 2;
    const int tci = (tid & 15) << 2;
    ull acc2[4][4];
    #pragma unroll
    for (int i=0;i<4;i++)
        #pragma unroll
        for (int k=0;k<4;k++) acc2[i][k] = 0ull;
    #pragma unroll 8
    for (int j = 0; j < Dd; j += 2){
        ull qf2[4], sf2[4];
        #pragma unroll
        for (int i=0;i<4;i++) qf2[i] = *(const ull*)&Qs[(tr+i)*TP + j];
        #pragma unroll
        for (int k=0;k<4;k++) sf2[k] = *(const ull*)&Ss[(tci+k)*TP + j];
        #pragma unroll
        for (int i=0;i<4;i++)
            #pragma unroll
            for (int k=0;k<4;k++) ffma2(acc2[i][k], qf2[i], sf2[k]);
    }
    #pragma unroll
    for (int i=0;i<4;i++){
        float gt_ = sg[tr + i];
        const size_t off = base + (size_t)(tr + i) * INNERx + tci;
        float4 old = *(const float4*)(Y + off);
        float f0 = fmaf(gt_, lo_of(acc2[i][0]) + hi_of(acc2[i][0]), old.x);
        float f1 = fmaf(gt_, lo_of(acc2[i][1]) + hi_of(acc2[i][1]), old.y);
        float f2 = fmaf(gt_, lo_of(acc2[i][2]) + hi_of(acc2[i][2]), old.z);
        float f3 = fmaf(gt_, lo_of(acc2[i][3]) + hi_of(acc2[i][3]), old.w);
        bf16 h0 = __float2bfloat16(f0), h1 = __float2bfloat16(f1);
        bf16 h2 = __float2bfloat16(f2), h3 = __float2bfloat16(f3);
        bf16 l0 = __float2bfloat16(f0 - __bfloat162float(h0));
        bf16 l1 = __float2bfloat16(f1 - __bfloat162float(h1));
        bf16 l2 = __float2bfloat16(f2 - __bfloat162float(h2));
        bf16 l3 = __float2bfloat16(f3 - __bfloat162float(h3));
        __nv_bfloat162* hp = (__nv_bfloat162*)(Yh + off);
        __nv_bfloat162* lp = (__nv_bfloat162*)(Yl + off);
        hp[0] = __nv_bfloat162{h0, h1}; hp[1] = __nv_bfloat162{h2, h3};
        lp[0] = __nv_bfloat162{l0, l1}; lp[1] = __nv_bfloat162{l2, l3};
    }
}

// ---------------- launcher -----------------------------------------------------
extern "C" void kernel_launch(void* const* d_in, const int* in_sizes, int n_in,
                              void* d_out, int out_size){
    const float* x     = (const float*)d_in[0];
    const float* state = (const float*)d_in[1];
    const float* Wq    = (const float*)d_in[2];
    const float* Wk    = (const float*)d_in[3];
    const float* Wv    = (const float*)d_in[4];
    const float* Wa    = (const float*)d_in[5];
    const float* ba    = (const float*)d_in[6];
    const float* Wb    = (const float*)d_in[7];
    const float* bb    = (const float*)d_in[8];
    const float* Wo    = (const float*)d_in[9];

    float* out      = (float*)d_out;
    float* stateOut = out + (size_t)ROWS * DMx;

    float *Q, *K, *V, *Y, *al, *be, *U, *Sc, *G, *gt;
    bf16 *xh, *xl, *yh, *yl;
    cudaGetSymbolAddress((void**)&Q,  g_Q);
    cudaGetSymbolAddress((void**)&K,  g_K);
    cudaGetSymbolAddress((void**)&V,  g_V);
    cudaGetSymbolAddress((void**)&Y,  g_Y);
    cudaGetSymbolAddress((void**)&al, g_alpha);
    cudaGetSymbolAddress((void**)&be, g_beta);
    cudaGetSymbolAddress((void**)&U,  g_U);
    cudaGetSymbolAddress((void**)&Sc, g_Sc);
    cudaGetSymbolAddress((void**)&G,  g_G);
    cudaGetSymbolAddress((void**)&gt, g_gt);
    cudaGetSymbolAddress((void**)&xh, g_xh);
    cudaGetSymbolAddress((void**)&xl, g_xl);
    cudaGetSymbolAddress((void**)&yh, g_yh);
    cudaGetSymbolAddress((void**)&yl, g_yl);

    cudaFuncSetAttribute(gemm_qkv,    cudaFuncAttributeMaxDynamicSharedMemorySize, GEMM_SMEM);
    cudaFuncSetAttribute(gemm_out,    cudaFuncAttributeMaxDynamicSharedMemorySize, GEMM_SMEM);
    cudaFuncSetAttribute(chunk_intra, cudaFuncAttributeMaxDynamicSharedMemorySize, INTRA_SMEM);

    // conversions (weights transposed in one launch so gemm_qkv is launch #4)
    conv_split<<<ROWS * DMx / 1024, 256>>>(x, xh, xl);
    trans_split_all<<<dim3(32, 32, 4), 256>>>(Wq, Wk, Wv, Wo);
    ab_kernel<<<ROWS / 32, 256>>>(x, Wa, ba, Wb, bb, al, be);

    // fused Q/K/V projections (launch #4 — profiled)
    gemm_qkv<<<dim3(12, ROWS / 128), 256, GEMM_SMEM>>>(xh, xl, Q, K, V);

    // chunked linear-attention scan
    chunk_intra<<<dim3(NCH, BH), 256, INTRA_SMEM>>>(Q, K, V, al, be, Y, U, G, gt);
    chunk_scan<<<BH, 256>>>(U, G, state, Sc, stateOut);
    chunk_inter<<<dim3(NCH, BH), 256>>>(Q, Sc, gt, Y, yh, yl);

    // output projection
    gemm_out<<<dim3(DMx / 256, ROWS / 128), 256, GEMM_SMEM>>>(yh, yl, out);
}

// round 9
// speedup vs baseline: 1.3053x; 1.3053x over previous
#include <cuda_runtime.h>
#include <cuda_fp16.h>
#include <math.h>
#include <cstdint>

#define Bsz 4
#define Tsz 2048
#define DMx 1024
#define Hh  16
#define Dd  64
#define INNERx 1024
#define ROWS (Bsz*Tsz)   // 8192
#define CH 64
#define NCH (Tsz/CH)     // 32
#define BH (Bsz*Hh)      // 64
#define KDIM 1024
#define NCHUNKS 32       // 2*KDIM/64 (fp16 2-term split, K-chunk 64)

typedef unsigned long long ull;
typedef __half hf;

// ---------------- scratch ----------------
__device__ float g_Q[ROWS*INNERx];
__device__ float g_K[ROWS*INNERx];
__device__ float g_V[ROWS*INNERx];
__device__ float g_Y[ROWS*INNERx];
__device__ float g_alpha[ROWS*Hh];
__device__ float g_beta[ROWS*Hh];
__device__ float g_U[BH*NCH*Dd*Dd];
__device__ float g_Sc[BH*NCH*Dd*Dd];
__device__ float g_G[BH*NCH];
__device__ float g_gt[BH*Tsz];
__device__ hf g_xh[ROWS*DMx];
__device__ hf g_xl[ROWS*DMx];
__device__ hf g_yh[ROWS*INNERx];
__device__ hf g_yl[ROWS*INNERx];
__device__ hf g_wqh[DMx*INNERx];
__device__ hf g_wkh[DMx*INNERx];
__device__ hf g_wvh[DMx*INNERx];
__device__ hf g_woh[INNERx*DMx];

// ---------------- helpers ----------------
__device__ __forceinline__ uint32_t smem_to_u32(const void* p){
    uint32_t a;
    asm("{ .reg .u64 t; cvta.to.shared.u64 t, %1; cvt.u32.u64 %0, t; }" : "=r"(a) : "l"(p));
    return a;
}
__device__ __forceinline__ void cp_async16(uint32_t dst, const void* src){
    asm volatile("cp.async.cg.shared.global [%0], [%1], 16;" :: "r"(dst), "l"(src));
}
#define CP_COMMIT() asm volatile("cp.async.commit_group;" ::: "memory")
#define CP_WAIT(n)  asm volatile("cp.async.wait_group %0;" :: "n"(n) : "memory")

__device__ __forceinline__ void ldsm_x4(uint32_t* r, uint32_t addr){
    asm volatile("ldmatrix.sync.aligned.m8n8.x4.shared.b16 {%0,%1,%2,%3}, [%4];"
        : "=r"(r[0]), "=r"(r[1]), "=r"(r[2]), "=r"(r[3]) : "r"(addr));
}
__device__ __forceinline__ void mma_fp16(float* c, const uint32_t* a, const uint32_t* b){
    asm volatile(
        "mma.sync.aligned.m16n8k16.row.col.f32.f16.f16.f32 "
        "{%0,%1,%2,%3}, {%4,%5,%6,%7}, {%8,%9}, {%0,%1,%2,%3};"
        : "+f"(c[0]), "+f"(c[1]), "+f"(c[2]), "+f"(c[3])
        : "r"(a[0]), "r"(a[1]), "r"(a[2]), "r"(a[3]), "r"(b[0]), "r"(b[1]));
}
__device__ __forceinline__ ull pack_dup(float a){
    ull r; unsigned int u = __float_as_uint(a);
    asm("mov.b64 %0, {%1, %1};" : "=l"(r) : "r"(u));
    return r;
}
__device__ __forceinline__ void ffma2(ull& d, ull a, ull b){
    asm("fma.rn.f32x2 %0, %1, %2, %3;" : "=l"(d) : "l"(a), "l"(b), "l"(d));
}
__device__ __forceinline__ float lo_of(ull v){ return __uint_as_float((unsigned)(v & 0xffffffffull)); }
__device__ __forceinline__ float hi_of(ull v){ return __uint_as_float((unsigned)(v >> 32)); }

// ---------------- prep: x hi/lo split + 4 weight transposes (one launch) -------
// blocks [0, 8192): x conv; blocks [8192, 12288): weight transpose tiles
__global__ __launch_bounds__(256)
void prep_kernel(const float* __restrict__ x,
                 const float* __restrict__ W0, const float* __restrict__ W1,
                 const float* __restrict__ W2, const float* __restrict__ W3){
    __shared__ float ts[32][33];
    const int bid = blockIdx.x, tid = threadIdx.x;
    if (bid < 8192){
        const size_t i = (size_t)bid * 256 + tid;
        float4 v = *(const float4*)(x + i * 4);
        hf h0 = __float2half(v.x), h1 = __float2half(v.y);
        hf h2 = __float2half(v.z), h3 = __float2half(v.w);
        hf l0 = __float2half(v.x - __half2float(h0));
        hf l1 = __float2half(v.y - __half2float(h1));
        hf l2 = __float2half(v.z - __half2float(h2));
        hf l3 = __float2half(v.w - __half2float(h3));
        __half2* hp = (__half2*)(g_xh + i * 4);
        __half2* lp = (__half2*)(g_xl + i * 4);
        hp[0] = __half2{h0, h1}; hp[1] = __half2{h2, h3};
        lp[0] = __half2{l0, l1}; lp[1] = __half2{l2, l3};
    } else {
        const int wz = bid - 8192;            // 0..4095
        const int z = wz >> 10;               // weight index
        const int rem = wz & 1023;
        const float* W = (z == 0) ? W0 : (z == 1) ? W1 : (z == 2) ? W2 : W3;
        hf* Th = (z == 0) ? g_wqh : (z == 1) ? g_wkh : (z == 2) ? g_wvh : g_woh;
        const int k0 = (rem >> 5) * 32, n0 = (rem & 31) * 32;
        const int tx = tid & 31, ty = tid >> 5;
        for (int i = ty; i < 32; i += 8)
            ts[i][tx] = W[(size_t)(k0 + i) * 1024 + n0 + tx];
        __syncthreads();
        for (int i = ty; i < 32; i += 8)
            Th[(size_t)(n0 + i) * 1024 + k0 + tx] = __float2half(ts[tx][i]);
    }
}

// ---------------- fp16 2-term mma.sync GEMM core -------------------------------
// C = (Ah + Al) @ Bh^T.  128x128 CTA tile, 8 warps (2x4) of 64x32, K-chunk 64,
// 3-stage cp.async, single __syncthreads per chunk. Extended K = 2048, 32 chunks.
#define STAGE_BYTES 32768          // A 16KB + B 16KB per stage
#define GEMM_SMEM   (3*STAGE_BYTES)

__device__ __forceinline__ void gemm_core(
    const hf* __restrict__ Ah, const hf* __restrict__ Al,
    const hf* __restrict__ Bh,
    float* __restrict__ C, int N, int bm, int bn)
{
    extern __shared__ __align__(128) char sm[];
    const uint32_t sb = smem_to_u32(sm);
    const int tid = threadIdx.x, lane = tid & 31, wid = tid >> 5;
    const int wm = wid >> 2, wn = wid & 3;

    float acc[4][4][4];
    #pragma unroll
    for (int mt = 0; mt < 4; mt++)
        #pragma unroll
        for (int nt = 0; nt < 4; nt++)
            #pragma unroll
            for (int e = 0; e < 4; e++) acc[mt][nt][e] = 0.f;

    const int urow = tid >> 3, uu = tid & 7;
    const int ubo = urow * 128 + uu * 16;
    const uint32_t uph = ubo ^ ((ubo >> 3) & 0x70);

    auto issue_stage = [&](int buf, int c){
        const int p = c >> 4, kk0 = (c & 15) << 6;
        const hf* As = (p == 1) ? Al : Ah;
        const uint32_t abase = sb + buf * STAGE_BYTES;
        const uint32_t bbase = abase + 16384;
        #pragma unroll
        for (int i = 0; i < 4; i++){
            const int row = urow + i * 32;
            const uint32_t dph = uph + i * 4096;
            cp_async16(abase + dph, As + (size_t)(bm + row) * KDIM + kk0 + uu * 8);
            cp_async16(bbase + dph, Bh + (size_t)(bn + row) * KDIM + kk0 + uu * 8);
        }
    };

    issue_stage(0, 0); CP_COMMIT();
    issue_stage(1, 1); CP_COMMIT();
    int buf = 0;
    for (int c = 0; c < NCHUNKS; c++){
        if (c >= NCHUNKS - 2) { CP_WAIT(0); } else { CP_WAIT(1); }
        __syncthreads();
        if (c + 2 < NCHUNKS){
            int nb = buf + 2; if (nb >= 3) nb -= 3;
            issue_stage(nb, c + 2); CP_COMMIT();
        }
        const uint32_t abase = sb + buf * STAGE_BYTES;
        const uint32_t bbase = abase + 16384;
        #pragma unroll
        for (int ks = 0; ks < 4; ks++){
            uint32_t afr[4][4];
            #pragma unroll
            for (int mt = 0; mt < 4; mt++){
                const int row = wm * 64 + mt * 16 + (lane & 15);
                const int bo = row * 128 + ks * 32 + ((lane >> 4) << 4);
                ldsm_x4(afr[mt], abase + (bo ^ ((bo >> 3) & 0x70)));
            }
            uint32_t bfr[2][4];
            #pragma unroll
            for (int np = 0; np < 2; np++){
                const int g = lane >> 3;
                const int row = wn * 32 + np * 16 + ((g >> 1) << 3) + (lane & 7);
                const int bo = row * 128 + ks * 32 + ((g & 1) << 4);
                ldsm_x4(bfr[np], bbase + (bo ^ ((bo >> 3) & 0x70)));
            }
            #pragma unroll
            for (int mt = 0; mt < 4; mt++)
                #pragma unroll
                for (int nt = 0; nt < 4; nt++)
                    mma_fp16(acc[mt][nt], afr[mt], &bfr[nt >> 1][(nt & 1) * 2]);
        }
        __syncthreads();
        buf++; if (buf >= 3) buf = 0;
    }

    const int r0 = lane >> 2, cb = (lane & 3) << 1;
    #pragma unroll
    for (int mt = 0; mt < 4; mt++){
        const int grow = bm + wm * 64 + mt * 16 + r0;
        #pragma unroll
        for (int nt = 0; nt < 4; nt++){
            const int gcol = bn + wn * 32 + nt * 8 + cb;
            *(float2*)(C + (size_t)grow * N + gcol) =
                make_float2(acc[mt][nt][0], acc[mt][nt][1]);
            *(float2*)(C + (size_t)(grow + 8) * N + gcol) =
                make_float2(acc[mt][nt][2], acc[mt][nt][3]);
        }
    }
}

// fused Q/K/V projection: grid (24, 64)
__global__ __launch_bounds__(256, 2)
void gemm_qkv(const hf* __restrict__ Ah, const hf* __restrict__ Al,
              float* __restrict__ Q, float* __restrict__ K, float* __restrict__ V){
    const int sel = blockIdx.x >> 3;
    const int bn = (blockIdx.x & 7) * 128;
    const int bm = blockIdx.y * 128;
    const hf* Bh = (sel == 0) ? g_wqh : (sel == 1) ? g_wkh : g_wvh;
    float* C = (sel == 0) ? Q : (sel == 1) ? K : V;
    gemm_core(Ah, Al, Bh, C, INNERx, bm, bn);
}

__global__ __launch_bounds__(256, 2)
void gemm_out(const hf* __restrict__ Ah, const hf* __restrict__ Al,
              float* __restrict__ C){
    gemm_core(Ah, Al, g_woh, C, DMx, blockIdx.y * 128, blockIdx.x * 128);
}

// ---------------- alpha/beta gate GEMM ----------------
__global__ __launch_bounds__(256)
void ab_kernel(const float* __restrict__ x,
               const float* __restrict__ Wa, const float* __restrict__ ba,
               const float* __restrict__ Wb, const float* __restrict__ bb,
               float* __restrict__ alpha, float* __restrict__ beta){
    __shared__ float xs[32][40];
    __shared__ float Ws[32][32];
    const int tid = threadIdx.x;
    const int r = tid >> 3, sub = tid & 7;
    const int row0 = blockIdx.x * 32;
    ull acc[2] = {0ull, 0ull};
    for (int k0 = 0; k0 < DMx; k0 += 32){
        #pragma unroll
        for (int q = 0; q < 4; q++){
            int idx = tid + q * 256;
            int kk = idx >> 5, cc = idx & 31;
            Ws[kk][cc] = (cc < 16) ? Wa[(size_t)(k0 + kk) * Hh + cc]
                                   : Wb[(size_t)(k0 + kk) * Hh + cc - 16];
        }
        {
            const int rr = tid >> 3, seg = tid & 7;
            float4 v = *(const float4*)(x + (size_t)(row0 + rr) * DMx + k0 + seg * 4);
            *(float4*)&xs[rr][seg * 4] = v;
        }
        __syncthreads();
        #pragma unroll
        for (int kk = 0; kk < 32; kk++){
            ull xv = pack_dup(xs[r][kk]);
            const ull* wp = (const ull*)&Ws[kk][sub * 4];
            ffma2(acc[0], xv, wp[0]);
            ffma2(acc[1], xv, wp[1]);
        }
        __syncthreads();
    }
    #pragma unroll
    for (int j = 0; j < 2; j++){
        float lo = lo_of(acc[j]), hi = hi_of(acc[j]);
        #pragma unroll
        for (int p = 0; p < 2; p++){
            float v = p ? hi : lo;
            int cc = sub * 4 + j * 2 + p;
            float bias = (cc < 16) ? ba[cc] : bb[cc - 16];
            float sig = 1.f / (1.f + expf(-(v + bias)));
            if (cc < 16) alpha[(size_t)(row0 + r) * Hh + cc] = sig;
            else         beta [(size_t)(row0 + r) * Hh + cc - 16] = sig;
        }
    }
}

// ---------------- K1: intra-chunk attention + chunk summary --------------------
#define TP 66
#define INTRA_SMEM ((3*64*TP + 192) * 4)

__global__ __launch_bounds__(256)
void chunk_intra(const float* __restrict__ Q, const float* __restrict__ K,
                 const float* __restrict__ V,
                 const float* __restrict__ alpha, const float* __restrict__ beta,
                 float* __restrict__ Yout, float* __restrict__ U,
                 float* __restrict__ Gout, float* __restrict__ gt_out){
    extern __shared__ float smf[];
    float* Qs  = smf;
    float* Ks  = smf + 64*TP;
    float* Vs  = smf + 2*64*TP;
    float* slg = smf + 3*64*TP;
    float* sb  = slg + 64;
    float* sw  = sb + 64;

    const int c  = blockIdx.x;
    const int bh = blockIdx.y;
    const int b  = bh >> 4, h = bh & 15;
    const int tid = threadIdx.x;
    const size_t base = ((size_t)(b * Tsz + c * CH) * Hh + h) * Dd;

    {
        const int r = tid >> 2, quad = tid & 3;
        const size_t off = base + (size_t)r * INNERx + quad * 16;
        float4 q0 = *(const float4*)(Q + off),     q1 = *(const float4*)(Q + off + 4);
        float4 q2 = *(const float4*)(Q + off + 8), q3 = *(const float4*)(Q + off + 12);
        float4 k0 = *(const float4*)(K + off),     k1 = *(const float4*)(K + off + 4);
        float4 k2 = *(const float4*)(K + off + 8), k3 = *(const float4*)(K + off + 12);
        float4 v0 = *(const float4*)(V + off),     v1 = *(const float4*)(V + off + 4);
        float4 v2 = *(const float4*)(V + off + 8), v3 = *(const float4*)(V + off + 12);
        float ss = k0.x*k0.x + k0.y*k0.y + k0.z*k0.z + k0.w*k0.w
                 + k1.x*k1.x + k1.y*k1.y + k1.z*k1.z + k1.w*k1.w
                 + k2.x*k2.x + k2.y*k2.y + k2.z*k2.z + k2.w*k2.w
                 + k3.x*k3.x + k3.y*k3.y + k3.z*k3.z + k3.w*k3.w;
        ss += __shfl_xor_sync(0xffffffffu, ss, 1);
        ss += __shfl_xor_sync(0xffffffffu, ss, 2);
        float inv = 1.f / fmaxf(sqrtf(ss), 1e-12f);
        float* qr = Qs + r * TP + quad * 16;
        float* kr = Ks + r * TP + quad * 16;
        float* vr = Vs + r * TP + quad * 16;
        qr[0]=q0.x; qr[1]=q0.y; qr[2]=q0.z; qr[3]=q0.w;
        qr[4]=q1.x; qr[5]=q1.y; qr[6]=q1.z; qr[7]=q1.w;
        qr[8]=q2.x; qr[9]=q2.y; qr[10]=q2.z; qr[11]=q2.w;
        qr[12]=q3.x; qr[13]=q3.y; qr[14]=q3.z; qr[15]=q3.w;
        kr[0]=k0.x*inv; kr[1]=k0.y*inv; kr[2]=k0.z*inv; kr[3]=k0.w*inv;
        kr[4]=k1.x*inv; kr[5]=k1.y*inv; kr[6]=k1.z*inv; kr[7]=k1.w*inv;
        kr[8]=k2.x*inv; kr[9]=k2.y*inv; kr[10]=k2.z*inv; kr[11]=k2.w*inv;
        kr[12]=k3.x*inv; kr[13]=k3.y*inv; kr[14]=k3.z*inv; kr[15]=k3.w*inv;
        vr[0]=v0.x; vr[1]=v0.y; vr[2]=v0.z; vr[3]=v0.w;
        vr[4]=v1.x; vr[5]=v1.y; vr[6]=v1.z; vr[7]=v1.w;
        vr[8]=v2.x; vr[9]=v2.y; vr[10]=v2.z; vr[11]=v2.w;
        vr[12]=v3.x; vr[13]=v3.y; vr[14]=v3.z; vr[15]=v3.w;
    }
    if (tid < 64){
        size_t gidx = (size_t)(b * Tsz + c * CH + tid) * Hh + h;
        slg[tid] = __logf(alpha[gidx]);
        sb[tid]  = beta[gidx];
    }
    __syncthreads();
    // parallel inclusive prefix sum over slg[0..63] (two warps + offset fix)
    if (tid < 64){
        const int lane = tid & 31;
        float v = slg[tid];
        #pragma unroll
        for (int o = 1; o < 32; o <<= 1){
            float n = __shfl_up_sync(0xffffffffu, v, o);
            if (lane >= o) v += n;
        }
        slg[tid] = v;
    }
    __syncthreads();
    if (tid >= 32 && tid < 64) slg[tid] += slg[31];
    __syncthreads();
    if (tid < 64){
        float lg_last = slg[63];
        sw[tid] = __expf(lg_last - slg[tid]) * sb[tid];
        float g = __expf(slg[tid]);
        gt_out[(size_t)bh * Tsz + c * CH + tid] = g;
        if (tid == 63) Gout[bh * NCH + c] = g;
    }
    __syncthreads();

    const int tr  = (tid >> 4) << 2;
    const int tc4 = (tid & 15) << 2;

    ull accM2[4][4];
    #pragma unroll
    for (int i=0;i<4;i++)
        #pragma unroll
        for (int j=0;j<4;j++) accM2[i][j] = 0ull;
    #pragma unroll 8
    for (int d = 0; d < Dd; d += 2){
        ull q2[4], k2[4];
        #pragma unroll
        for (int i=0;i<4;i++) q2[i] = *(const ull*)&Qs[(tr+i)*TP + d];
        #pragma unroll
        for (int j=0;j<4;j++) k2[j] = *(const ull*)&Ks[(tc4+j)*TP + d];
        #pragma unroll
        for (int i=0;i<4;i++)
            #pragma unroll
            for (int j=0;j<4;j++) ffma2(accM2[i][j], q2[i], k2[j]);
    }
    __syncthreads();
    #pragma unroll
    for (int i=0;i<4;i++){
        int tau = tr + i;
        float lgt = slg[tau];
        #pragma unroll
        for (int j=0;j<4;j++){
            int jj = tc4 + j;
            float p = 0.f;
            if (tau >= jj)
                p = __expf(lgt - slg[jj]) * sb[jj] * (lo_of(accM2[i][j]) + hi_of(accM2[i][j]));
            Qs[tau*TP + jj] = p;
        }
    }
    __syncthreads();

    ull accY2[4][2], accU2[4][2];
    #pragma unroll
    for (int i=0;i<4;i++){
        accY2[i][0]=0ull; accY2[i][1]=0ull; accU2[i][0]=0ull; accU2[i][1]=0ull;
    }
    #pragma unroll 4
    for (int j = 0; j < CH; j++){
        float wj = sw[j];
        ull vf0 = *(const ull*)&Vs[j*TP + tc4];
        ull vf1 = *(const ull*)&Vs[j*TP + tc4 + 2];
        ull kf0 = *(const ull*)&Ks[j*TP + tc4];
        ull kf1 = *(const ull*)&Ks[j*TP + tc4 + 2];
        #pragma unroll
        for (int i=0;i<4;i++){
            ull pf = pack_dup(Qs[(tr+i)*TP + j]);
            ull vu = pack_dup(Vs[j*TP + tr + i] * wj);
            ffma2(accY2[i][0], pf, vf0);
            ffma2(accY2[i][1], pf, vf1);
            ffma2(accU2[i][0], vu, kf0);
            ffma2(accU2[i][1], vu, kf1);
        }
    }
    #pragma unroll
    for (int i=0;i<4;i++){
        float* yr = Yout + base + (size_t)(tr + i) * INNERx + tc4;
        *(float4*)yr = make_float4(lo_of(accY2[i][0]), hi_of(accY2[i][0]),
                                   lo_of(accY2[i][1]), hi_of(accY2[i][1]));
        float* ur = U + ((size_t)(bh * NCH + c) * 4096) + (tr + i) * 64 + tc4;
        *(float4*)ur = make_float4(lo_of(accU2[i][0]), hi_of(accU2[i][0]),
                                   lo_of(accU2[i][1]), hi_of(accU2[i][1]));
    }
}

// ---------------- K2: chunk-level state scan -----------------------------------
__global__ __launch_bounds__(256)
void chunk_scan(const float* __restrict__ U, const float* __restrict__ G,
                const float* __restrict__ state0,
                float* __restrict__ Sc, float* __restrict__ stateOut){
    const int bh = blockIdx.x;
    const int tid = threadIdx.x;
    float S[16];
    const size_t bs = (size_t)bh * 4096;
    #pragma unroll
    for (int j = 0; j < 16; j++) S[j] = state0[bs + j * 256 + tid];
    for (int c = 0; c < NCH; c++){
        const size_t uc = ((size_t)(bh * NCH + c)) * 4096;
        float g = __ldg(&G[bh * NCH + c]);
        float u[16];
        #pragma unroll
        for (int j = 0; j < 16; j++) u[j] = U[uc + j * 256 + tid];
        #pragma unroll
        for (int j = 0; j < 16; j++){
            Sc[uc + j * 256 + tid] = S[j];
            S[j] = fmaf(g, S[j], u[j]);
        }
    }
    #pragma unroll
    for (int j = 0; j < 16; j++) stateOut[bs + j * 256 + tid] = S[j];
}

// ---------------- K3: Y += diag(g) Q S^T ; emit fp16 hi/lo split of Y ----------
__global__ __launch_bounds__(256)
void chunk_inter(const float* __restrict__ Q, const float* __restrict__ Sc,
                 const float* __restrict__ gt, const float* __restrict__ Y,
                 hf* __restrict__ Yh, hf* __restrict__ Yl){
    __shared__ float Qs[64*TP];
    __shared__ float Ss[64*TP];
    __shared__ float sg[64];
    const int c  = blockIdx.x;
    const int bh = blockIdx.y;
    const int b  = bh >> 4, h = bh & 15;
    const int tid = threadIdx.x;
    const size_t base = ((size_t)(b * Tsz + c * CH) * Hh + h) * Dd;
    {
        const int r = tid >> 2, quad = tid & 3;
        const size_t off = base + (size_t)r * INNERx + quad * 16;
        const size_t soff = ((size_t)(bh * NCH + c)) * 4096 + r * 64 + quad * 16;
        #pragma unroll
        for (int l = 0; l < 16; l += 4){
            float4 qv = *(const float4*)(Q + off + l);
            float4 sv = *(const float4*)(Sc + soff + l);
            float* qr = Qs + r * TP + quad * 16 + l;
            float* sr = Ss + r * TP + quad * 16 + l;
            qr[0]=qv.x; qr[1]=qv.y; qr[2]=qv.z; qr[3]=qv.w;
            sr[0]=sv.x; sr[1]=sv.y; sr[2]=sv.z; sr[3]=sv.w;
        }
    }
    if (tid < 64) sg[tid] = gt[(size_t)bh * Tsz + c * CH + tid];
    __syncthreads();
    const int tr  = (tid >> 4) << 2;
    const int tci = (tid & 15) << 2;
    ull acc2[4][4];
    #pragma unroll
    for (int i=0;i<4;i++)
        #pragma unroll
        for (int k=0;k<4;k++) acc2[i][k] = 0ull;
    #pragma unroll 8
    for (int j = 0; j < Dd; j += 2){
        ull qf2[4], sf2[4];
        #pragma unroll
        for (int i=0;i<4;i++) qf2[i] = *(const ull*)&Qs[(tr+i)*TP + j];
        #pragma unroll
        for (int k=0;k<4;k++) sf2[k] = *(const ull*)&Ss[(tci+k)*TP + j];
        #pragma unroll
        for (int i=0;i<4;i++)
            #pragma unroll
            for (int k=0;k<4;k++) ffma2(acc2[i][k], qf2[i], sf2[k]);
    }
    #pragma unroll
    for (int i=0;i<4;i++){
        float gt_ = sg[tr + i];
        const size_t off = base + (size_t)(tr + i) * INNERx + tci;
        float4 old = *(const float4*)(Y + off);
        float f0 = fmaf(gt_, lo_of(acc2[i][0]) + hi_of(acc2[i][0]), old.x);
        float f1 = fmaf(gt_, lo_of(acc2[i][1]) + hi_of(acc2[i][1]), old.y);
        float f2 = fmaf(gt_, lo_of(acc2[i][2]) + hi_of(acc2[i][2]), old.z);
        float f3 = fmaf(gt_, lo_of(acc2[i][3]) + hi_of(acc2[i][3]), old.w);
        hf h0 = __float2half(f0), h1 = __float2half(f1);
        hf h2 = __float2half(f2), h3 = __float2half(f3);
        hf l0 = __float2half(f0 - __half2float(h0));
        hf l1 = __float2half(f1 - __half2float(h1));
        hf l2 = __float2half(f2 - __half2float(h2));
        hf l3 = __float2half(f3 - __half2float(h3));
        __half2* hp = (__half2*)(Yh + off);
        __half2* lp = (__half2*)(Yl + off);
        hp[0] = __half2{h0, h1}; hp[1] = __half2{h2, h3};
        lp[0] = __half2{l0, l1}; lp[1] = __half2{l2, l3};
    }
}

// ---------------- launcher -----------------------------------------------------
extern "C" void kernel_launch(void* const* d_in, const int* in_sizes, int n_in,
                              void* d_out, int out_size){
    const float* x     = (const float*)d_in[0];
    const float* state = (const float*)d_in[1];
    const float* Wq    = (const float*)d_in[2];
    const float* Wk    = (const float*)d_in[3];
    const float* Wv    = (const float*)d_in[4];
    const float* Wa    = (const float*)d_in[5];
    const float* ba    = (const float*)d_in[6];
    const float* Wb    = (const float*)d_in[7];
    const float* bb    = (const float*)d_in[8];
    const float* Wo    = (const float*)d_in[9];

    float* out      = (float*)d_out;
    float* stateOut = out + (size_t)ROWS * DMx;

    float *Q, *K, *V, *Y, *al, *be, *U, *Sc, *G, *gt;
    hf *xh, *xl, *yh, *yl;
    cudaGetSymbolAddress((void**)&Q,  g_Q);
    cudaGetSymbolAddress((void**)&K,  g_K);
    cudaGetSymbolAddress((void**)&V,  g_V);
    cudaGetSymbolAddress((void**)&Y,  g_Y);
    cudaGetSymbolAddress((void**)&al, g_alpha);
    cudaGetSymbolAddress((void**)&be, g_beta);
    cudaGetSymbolAddress((void**)&U,  g_U);
    cudaGetSymbolAddress((void**)&Sc, g_Sc);
    cudaGetSymbolAddress((void**)&G,  g_G);
    cudaGetSymbolAddress((void**)&gt, g_gt);
    cudaGetSymbolAddress((void**)&xh, g_xh);
    cudaGetSymbolAddress((void**)&xl, g_xl);
    cudaGetSymbolAddress((void**)&yh, g_yh);
    cudaGetSymbolAddress((void**)&yl, g_yl);

    cudaFuncSetAttribute(gemm_qkv,    cudaFuncAttributeMaxDynamicSharedMemorySize, GEMM_SMEM);
    cudaFuncSetAttribute(gemm_out,    cudaFuncAttributeMaxDynamicSharedMemorySize, GEMM_SMEM);
    cudaFuncSetAttribute(chunk_intra, cudaFuncAttributeMaxDynamicSharedMemorySize, INTRA_SMEM);

    // prep: x split + all weight transposes (launch #1)
    prep_kernel<<<8192 + 4096, 256>>>(x, Wq, Wk, Wv, Wo);
    // gates (launch #2)
    ab_kernel<<<ROWS / 32, 256>>>(x, Wa, ba, Wb, bb, al, be);
    // fused Q/K/V projections (launch #3)
    gemm_qkv<<<dim3(24, ROWS / 128), 256, GEMM_SMEM>>>(xh, xl, Q, K, V);
    // chunked linear-attention scan (chunk_intra = launch #4 -> profiled)
    chunk_intra<<<dim3(NCH, BH), 256, INTRA_SMEM>>>(Q, K, V, al, be, Y, U, G, gt);
    chunk_scan<<<BH, 256>>>(U, G, state, Sc, stateOut);
    chunk_inter<<<dim3(NCH, BH), 256>>>(Q, Sc, gt, Y, yh, yl);
    // output projection
    gemm_out<<<dim3(DMx / 128, ROWS / 128), 256, GEMM_SMEM>>>(yh, yl, out);
}

// round 11
// speedup vs baseline: 1.5318x; 1.1735x over previous
#include <cuda_runtime.h>
#include <cuda_fp16.h>
#include <math.h>
#include <cstdint>

#define Bsz 4
#define Tsz 2048
#define DMx 1024
#define Hh  16
#define Dd  64
#define INNERx 1024
#define ROWS (Bsz*Tsz)   // 8192
#define CH 64
#define NCH (Tsz/CH)     // 32
#define BH (Bsz*Hh)      // 64
#define KDIM 1024
#define NCHUNKS 32       // 2*KDIM/64 (fp16 2-term split, K-chunk 64)

typedef unsigned long long ull;
typedef __half hf;

// ---------------- scratch ----------------
__device__ float g_Q[ROWS*INNERx];
__device__ float g_K[ROWS*INNERx];
__device__ float g_V[ROWS*INNERx];
__device__ float g_Y[ROWS*INNERx];
__device__ float g_alpha[ROWS*Hh];
__device__ float g_beta[ROWS*Hh];
__device__ float g_U[BH*NCH*Dd*Dd];
__device__ float g_Sc[BH*NCH*Dd*Dd];
__device__ float g_G[BH*NCH];
__device__ float g_gt[BH*Tsz];
__device__ hf g_xh[ROWS*DMx];
__device__ hf g_xl[ROWS*DMx];
__device__ hf g_yh[ROWS*INNERx];
__device__ hf g_yl[ROWS*INNERx];
__device__ hf g_wqh[DMx*INNERx];
__device__ hf g_wkh[DMx*INNERx];
__device__ hf g_wvh[DMx*INNERx];
__device__ hf g_woh[INNERx*DMx];

// ---------------- helpers ----------------
__device__ __forceinline__ uint32_t smem_to_u32(const void* p){
    uint32_t a;
    asm("{ .reg .u64 t; cvta.to.shared.u64 t, %1; cvt.u32.u64 %0, t; }" : "=r"(a) : "l"(p));
    return a;
}
__device__ __forceinline__ void cp_async16(uint32_t dst, const void* src){
    asm volatile("cp.async.cg.shared.global [%0], [%1], 16;" :: "r"(dst), "l"(src));
}
#define CP_COMMIT() asm volatile("cp.async.commit_group;" ::: "memory")
#define CP_WAIT(n)  asm volatile("cp.async.wait_group %0;" :: "n"(n) : "memory")

__device__ __forceinline__ void ldsm_x4(uint32_t* r, uint32_t addr){
    asm volatile("ldmatrix.sync.aligned.m8n8.x4.shared.b16 {%0,%1,%2,%3}, [%4];"
        : "=r"(r[0]), "=r"(r[1]), "=r"(r[2]), "=r"(r[3]) : "r"(addr));
}
__device__ __forceinline__ void mma_fp16(float* c, const uint32_t* a, const uint32_t* b){
    asm volatile(
        "mma.sync.aligned.m16n8k16.row.col.f32.f16.f16.f32 "
        "{%0,%1,%2,%3}, {%4,%5,%6,%7}, {%8,%9}, {%0,%1,%2,%3};"
        : "+f"(c[0]), "+f"(c[1]), "+f"(c[2]), "+f"(c[3])
        : "r"(a[0]), "r"(a[1]), "r"(a[2]), "r"(a[3]), "r"(b[0]), "r"(b[1]));
}
__device__ __forceinline__ ull pack_dup(float a){
    ull r; unsigned int u = __float_as_uint(a);
    asm("mov.b64 %0, {%1, %1};" : "=l"(r) : "r"(u));
    return r;
}
__device__ __forceinline__ void ffma2(ull& d, ull a, ull b){
    asm("fma.rn.f32x2 %0, %1, %2, %3;" : "=l"(d) : "l"(a), "l"(b), "l"(d));
}
__device__ __forceinline__ ull mul2(ull a, ull b){
    ull r; asm("mul.rn.f32x2 %0, %1, %2;" : "=l"(r) : "l"(a), "l"(b));
    return r;
}
__device__ __forceinline__ float lo_of(ull v){ return __uint_as_float((unsigned)(v & 0xffffffffull)); }
__device__ __forceinline__ float hi_of(ull v){ return __uint_as_float((unsigned)(v >> 32)); }

// ---------------- prep: x hi/lo split + 4 weight transposes (one launch) -------
__global__ __launch_bounds__(256)
void prep_kernel(const float* __restrict__ x,
                 const float* __restrict__ W0, const float* __restrict__ W1,
                 const float* __restrict__ W2, const float* __restrict__ W3){
    __shared__ float ts[32][33];
    const int bid = blockIdx.x, tid = threadIdx.x;
    if (bid < 8192){
        const size_t i = (size_t)bid * 256 + tid;
        float4 v = *(const float4*)(x + i * 4);
        hf h0 = __float2half(v.x), h1 = __float2half(v.y);
        hf h2 = __float2half(v.z), h3 = __float2half(v.w);
        hf l0 = __float2half(v.x - __half2float(h0));
        hf l1 = __float2half(v.y - __half2float(h1));
        hf l2 = __float2half(v.z - __half2float(h2));
        hf l3 = __float2half(v.w - __half2float(h3));
        __half2* hp = (__half2*)(g_xh + i * 4);
        __half2* lp = (__half2*)(g_xl + i * 4);
        hp[0] = __half2{h0, h1}; hp[1] = __half2{h2, h3};
        lp[0] = __half2{l0, l1}; lp[1] = __half2{l2, l3};
    } else {
        const int wz = bid - 8192;
        const int z = wz >> 10;
        const int rem = wz & 1023;
        const float* W = (z == 0) ? W0 : (z == 1) ? W1 : (z == 2) ? W2 : W3;
        hf* Th = (z == 0) ? g_wqh : (z == 1) ? g_wkh : (z == 2) ? g_wvh : g_woh;
        const int k0 = (rem >> 5) * 32, n0 = (rem & 31) * 32;
        const int tx = tid & 31, ty = tid >> 5;
        for (int i = ty; i < 32; i += 8)
            ts[i][tx] = W[(size_t)(k0 + i) * 1024 + n0 + tx];
        __syncthreads();
        for (int i = ty; i < 32; i += 8)
            Th[(size_t)(n0 + i) * 1024 + k0 + tx] = __float2half(ts[tx][i]);
    }
}

// ---------------- fp16 2-term mma.sync GEMM core -------------------------------
#define STAGE_BYTES 32768
#define GEMM_SMEM   (3*STAGE_BYTES)

__device__ __forceinline__ void gemm_core(
    const hf* __restrict__ Ah, const hf* __restrict__ Al,
    const hf* __restrict__ Bh,
    float* __restrict__ C, int N, int bm, int bn)
{
    extern __shared__ __align__(128) char sm[];
    const uint32_t sb = smem_to_u32(sm);
    const int tid = threadIdx.x, lane = tid & 31, wid = tid >> 5;
    const int wm = wid >> 2, wn = wid & 3;

    float acc[4][4][4];
    #pragma unroll
    for (int mt = 0; mt < 4; mt++)
        #pragma unroll
        for (int nt = 0; nt < 4; nt++)
            #pragma unroll
            for (int e = 0; e < 4; e++) acc[mt][nt][e] = 0.f;

    const int urow = tid >> 3, uu = tid & 7;
    const int ubo = urow * 128 + uu * 16;
    const uint32_t uph = ubo ^ ((ubo >> 3) & 0x70);

    auto issue_stage = [&](int buf, int c){
        const int p = c >> 4, kk0 = (c & 15) << 6;
        const hf* As = (p == 1) ? Al : Ah;
        const uint32_t abase = sb + buf * STAGE_BYTES;
        const uint32_t bbase = abase + 16384;
        #pragma unroll
        for (int i = 0; i < 4; i++){
            const int row = urow + i * 32;
            const uint32_t dph = uph + i * 4096;
            cp_async16(abase + dph, As + (size_t)(bm + row) * KDIM + kk0 + uu * 8);
            cp_async16(bbase + dph, Bh + (size_t)(bn + row) * KDIM + kk0 + uu * 8);
        }
    };

    issue_stage(0, 0); CP_COMMIT();
    issue_stage(1, 1); CP_COMMIT();
    int buf = 0;
    for (int c = 0; c < NCHUNKS; c++){
        if (c >= NCHUNKS - 2) { CP_WAIT(0); } else { CP_WAIT(1); }
        __syncthreads();
        if (c + 2 < NCHUNKS){
            int nb = buf + 2; if (nb >= 3) nb -= 3;
            issue_stage(nb, c + 2); CP_COMMIT();
        }
        const uint32_t abase = sb + buf * STAGE_BYTES;
        const uint32_t bbase = abase + 16384;
        #pragma unroll
        for (int ks = 0; ks < 4; ks++){
            uint32_t afr[4][4];
            #pragma unroll
            for (int mt = 0; mt < 4; mt++){
                const int row = wm * 64 + mt * 16 + (lane & 15);
                const int bo = row * 128 + ks * 32 + ((lane >> 4) << 4);
                ldsm_x4(afr[mt], abase + (bo ^ ((bo >> 3) & 0x70)));
            }
            uint32_t bfr[2][4];
            #pragma unroll
            for (int np = 0; np < 2; np++){
                const int g = lane >> 3;
                const int row = wn * 32 + np * 16 + ((g >> 1) << 3) + (lane & 7);
                const int bo = row * 128 + ks * 32 + ((g & 1) << 4);
                ldsm_x4(bfr[np], bbase + (bo ^ ((bo >> 3) & 0x70)));
            }
            #pragma unroll
            for (int mt = 0; mt < 4; mt++)
                #pragma unroll
                for (int nt = 0; nt < 4; nt++)
                    mma_fp16(acc[mt][nt], afr[mt], &bfr[nt >> 1][(nt & 1) * 2]);
        }
        __syncthreads();
        buf++; if (buf >= 3) buf = 0;
    }

    const int r0 = lane >> 2, cb = (lane & 3) << 1;
    #pragma unroll
    for (int mt = 0; mt < 4; mt++){
        const int grow = bm + wm * 64 + mt * 16 + r0;
        #pragma unroll
        for (int nt = 0; nt < 4; nt++){
            const int gcol = bn + wn * 32 + nt * 8 + cb;
            *(float2*)(C + (size_t)grow * N + gcol) =
                make_float2(acc[mt][nt][0], acc[mt][nt][1]);
            *(float2*)(C + (size_t)(grow + 8) * N + gcol) =
                make_float2(acc[mt][nt][2], acc[mt][nt][3]);
        }
    }
}

__global__ __launch_bounds__(256, 2)
void gemm_qkv(const hf* __restrict__ Ah, const hf* __restrict__ Al,
              float* __restrict__ Q, float* __restrict__ K, float* __restrict__ V){
    const int sel = blockIdx.x >> 3;
    const int bn = (blockIdx.x & 7) * 128;
    const int bm = blockIdx.y * 128;
    const hf* Bh = (sel == 0) ? g_wqh : (sel == 1) ? g_wkh : g_wvh;
    float* C = (sel == 0) ? Q : (sel == 1) ? K : V;
    gemm_core(Ah, Al, Bh, C, INNERx, bm, bn);
}

__global__ __launch_bounds__(256, 2)
void gemm_out(const hf* __restrict__ Ah, const hf* __restrict__ Al,
              float* __restrict__ C){
    gemm_core(Ah, Al, g_woh, C, DMx, blockIdx.y * 128, blockIdx.x * 128);
}

// ---------------- alpha/beta gate GEMM ----------------
__global__ __launch_bounds__(256)
void ab_kernel(const float* __restrict__ x,
               const float* __restrict__ Wa, const float* __restrict__ ba,
               const float* __restrict__ Wb, const float* __restrict__ bb,
               float* __restrict__ alpha, float* __restrict__ beta){
    __shared__ float xs[32][40];
    __shared__ float Ws[32][32];
    const int tid = threadIdx.x;
    const int r = tid >> 3, sub = tid & 7;
    const int row0 = blockIdx.x * 32;
    ull acc[2] = {0ull, 0ull};
    for (int k0 = 0; k0 < DMx; k0 += 32){
        #pragma unroll
        for (int q = 0; q < 4; q++){
            int idx = tid + q * 256;
            int kk = idx >> 5, cc = idx & 31;
            Ws[kk][cc] = (cc < 16) ? Wa[(size_t)(k0 + kk) * Hh + cc]
                                   : Wb[(size_t)(k0 + kk) * Hh + cc - 16];
        }
        {
            const int rr = tid >> 3, seg = tid & 7;
            float4 v = *(const float4*)(x + (size_t)(row0 + rr) * DMx + k0 + seg * 4);
            *(float4*)&xs[rr][seg * 4] = v;
        }
        __syncthreads();
        #pragma unroll
        for (int kk = 0; kk < 32; kk++){
            ull xv = pack_dup(xs[r][kk]);
            const ull* wp = (const ull*)&Ws[kk][sub * 4];
            ffma2(acc[0], xv, wp[0]);
            ffma2(acc[1], xv, wp[1]);
        }
        __syncthreads();
    }
    #pragma unroll
    for (int j = 0; j < 2; j++){
        float lo = lo_of(acc[j]), hi = hi_of(acc[j]);
        #pragma unroll
        for (int p = 0; p < 2; p++){
            float v = p ? hi : lo;
            int cc = sub * 4 + j * 2 + p;
            float bias = (cc < 16) ? ba[cc] : bb[cc - 16];
            float sig = 1.f / (1.f + expf(-(v + bias)));
            if (cc < 16) alpha[(size_t)(row0 + r) * Hh + cc] = sig;
            else         beta [(size_t)(row0 + r) * Hh + cc - 16] = sig;
        }
    }
}

// ---------------- K1: intra-chunk attention + chunk summary --------------------
// Lane remap: warp spans 4 row-groups x 8 col-groups -> all LDS 1 wavefront.
// P stored transposed (Pt[j][tau]) so Y/U phase uses only vector ull loads.
#define TP 66
#define INTRA_SMEM ((3*64*TP + 192) * 4)

__global__ __launch_bounds__(256)
void chunk_intra(const float* __restrict__ Q, const float* __restrict__ K,
                 const float* __restrict__ V,
                 const float* __restrict__ alpha, const float* __restrict__ beta,
                 float* __restrict__ Yout, float* __restrict__ U,
                 float* __restrict__ Gout, float* __restrict__ gt_out){
    extern __shared__ float smf[];
    float* Qs  = smf;
    float* Ks  = smf + 64*TP;
    float* Vs  = smf + 2*64*TP;
    float* slg = smf + 3*64*TP;
    float* sb  = slg + 64;
    float* sw  = sb + 64;

    const int c  = blockIdx.x;
    const int bh = blockIdx.y;
    const int b  = bh >> 4, h = bh & 15;
    const int tid = threadIdx.x;
    const size_t base = ((size_t)(b * Tsz + c * CH) * Hh + h) * Dd;

    {
        const int r = tid >> 2, quad = tid & 3;
        const size_t off = base + (size_t)r * INNERx + quad * 16;
        float4 q0 = *(const float4*)(Q + off),     q1 = *(const float4*)(Q + off + 4);
        float4 q2 = *(const float4*)(Q + off + 8), q3 = *(const float4*)(Q + off + 12);
        float4 k0 = *(const float4*)(K + off),     k1 = *(const float4*)(K + off + 4);
        float4 k2 = *(const float4*)(K + off + 8), k3 = *(const float4*)(K + off + 12);
        float4 v0 = *(const float4*)(V + off),     v1 = *(const float4*)(V + off + 4);
        float4 v2 = *(const float4*)(V + off + 8), v3 = *(const float4*)(V + off + 12);
        float ss = k0.x*k0.x + k0.y*k0.y + k0.z*k0.z + k0.w*k0.w
                 + k1.x*k1.x + k1.y*k1.y + k1.z*k1.z + k1.w*k1.w
                 + k2.x*k2.x + k2.y*k2.y + k2.z*k2.z + k2.w*k2.w
                 + k3.x*k3.x + k3.y*k3.y + k3.z*k3.z + k3.w*k3.w;
        ss += __shfl_xor_sync(0xffffffffu, ss, 1);
        ss += __shfl_xor_sync(0xffffffffu, ss, 2);
        float inv = 1.f / fmaxf(sqrtf(ss), 1e-12f);
        float* qr = Qs + r * TP + quad * 16;
        float* kr = Ks + r * TP + quad * 16;
        float* vr = Vs + r * TP + quad * 16;
        qr[0]=q0.x; qr[1]=q0.y; qr[2]=q0.z; qr[3]=q0.w;
        qr[4]=q1.x; qr[5]=q1.y; qr[6]=q1.z; qr[7]=q1.w;
        qr[8]=q2.x; qr[9]=q2.y; qr[10]=q2.z; qr[11]=q2.w;
        qr[12]=q3.x; qr[13]=q3.y; qr[14]=q3.z; qr[15]=q3.w;
        kr[0]=k0.x*inv; kr[1]=k0.y*inv; kr[2]=k0.z*inv; kr[3]=k0.w*inv;
        kr[4]=k1.x*inv; kr[5]=k1.y*inv; kr[6]=k1.z*inv; kr[7]=k1.w*inv;
        kr[8]=k2.x*inv; kr[9]=k2.y*inv; kr[10]=k2.z*inv; kr[11]=k2.w*inv;
        kr[12]=k3.x*inv; kr[13]=k3.y*inv; kr[14]=k3.z*inv; kr[15]=k3.w*inv;
        vr[0]=v0.x; vr[1]=v0.y; vr[2]=v0.z; vr[3]=v0.w;
        vr[4]=v1.x; vr[5]=v1.y; vr[6]=v1.z; vr[7]=v1.w;
        vr[8]=v2.x; vr[9]=v2.y; vr[10]=v2.z; vr[11]=v2.w;
        vr[12]=v3.x; vr[13]=v3.y; vr[14]=v3.z; vr[15]=v3.w;
    }
    if (tid < 64){
        size_t gidx = (size_t)(b * Tsz + c * CH + tid) * Hh + h;
        slg[tid] = __logf(alpha[gidx]);
        sb[tid]  = beta[gidx];
    }
    __syncthreads();
    if (tid < 64){
        const int lane = tid & 31;
        float v = slg[tid];
        #pragma unroll
        for (int o = 1; o < 32; o <<= 1){
            float n = __shfl_up_sync(0xffffffffu, v, o);
            if (lane >= o) v += n;
        }
        slg[tid] = v;
    }
    __syncthreads();
    if (tid >= 32 && tid < 64) slg[tid] += slg[31];
    __syncthreads();
    if (tid < 64){
        float lg_last = slg[63];
        sw[tid] = __expf(lg_last - slg[tid]) * sb[tid];
        float g = __expf(slg[tid]);
        gt_out[(size_t)bh * Tsz + c * CH + tid] = g;
        if (tid == 63) Gout[bh * NCH + c] = g;
    }
    __syncthreads();

    // lane-remapped tile indices: warp covers 4 row-groups x 8 col-groups
    const int lane = tid & 31, w = tid >> 5;
    const int tr  = (((w & 3) << 2) | (lane & 3)) << 2;
    const int tc4 = (((w >> 2) << 3) | (lane >> 2)) << 2;

    ull accM2[4][4];
    #pragma unroll
    for (int i=0;i<4;i++)
        #pragma unroll
        for (int j=0;j<4;j++) accM2[i][j] = 0ull;
    #pragma unroll 8
    for (int d = 0; d < Dd; d += 2){
        ull q2[4], k2[4];
        #pragma unroll
        for (int i=0;i<4;i++) q2[i] = *(const ull*)&Qs[(tr+i)*TP + d];
        #pragma unroll
        for (int j=0;j<4;j++) k2[j] = *(const ull*)&Ks[(tc4+j)*TP + d];
        #pragma unroll
        for (int i=0;i<4;i++)
            #pragma unroll
            for (int j=0;j<4;j++) ffma2(accM2[i][j], q2[i], k2[j]);
    }
    __syncthreads();
    // write gated+masked P TRANSPOSED: Pt[jj][tau]
    #pragma unroll
    for (int i=0;i<4;i++){
        int tau = tr + i;
        float lgt = slg[tau];
        #pragma unroll
        for (int j=0;j<4;j++){
            int jj = tc4 + j;
            float p = 0.f;
            if (tau >= jj)
                p = __expf(lgt - slg[jj]) * sb[jj] * (lo_of(accM2[i][j]) + hi_of(accM2[i][j]));
            Qs[jj*TP + tau] = p;
        }
    }
    __syncthreads();

    ull accY2[4][2], accU2[4][2];
    #pragma unroll
    for (int i=0;i<4;i++){
        accY2[i][0]=0ull; accY2[i][1]=0ull; accU2[i][0]=0ull; accU2[i][1]=0ull;
    }
    #pragma unroll 4
    for (int j = 0; j < CH; j++){
        ull wj2 = pack_dup(sw[j]);
        ull pt01 = *(const ull*)&Qs[j*TP + tr];
        ull pt23 = *(const ull*)&Qs[j*TP + tr + 2];
        ull vf0 = *(const ull*)&Vs[j*TP + tc4];
        ull vf1 = *(const ull*)&Vs[j*TP + tc4 + 2];
        ull vu01 = *(const ull*)&Vs[j*TP + tr];
        ull vu23 = *(const ull*)&Vs[j*TP + tr + 2];
        ull kw0 = mul2(*(const ull*)&Ks[j*TP + tc4], wj2);
        ull kw1 = mul2(*(const ull*)&Ks[j*TP + tc4 + 2], wj2);
        float pv[4] = {lo_of(pt01), hi_of(pt01), lo_of(pt23), hi_of(pt23)};
        float vv[4] = {lo_of(vu01), hi_of(vu01), lo_of(vu23), hi_of(vu23)};
        #pragma unroll
        for (int i=0;i<4;i++){
            ull pf = pack_dup(pv[i]);
            ull vu = pack_dup(vv[i]);
            ffma2(accY2[i][0], pf, vf0);
            ffma2(accY2[i][1], pf, vf1);
            ffma2(accU2[i][0], vu, kw0);
            ffma2(accU2[i][1], vu, kw1);
        }
    }
    #pragma unroll
    for (int i=0;i<4;i++){
        float* yr = Yout + base + (size_t)(tr + i) * INNERx + tc4;
        *(float4*)yr = make_float4(lo_of(accY2[i][0]), hi_of(accY2[i][0]),
                                   lo_of(accY2[i][1]), hi_of(accY2[i][1]));
        float* ur = U + ((size_t)(bh * NCH + c) * 4096) + (tr + i) * 64 + tc4;
        *(float4*)ur = make_float4(lo_of(accU2[i][0]), hi_of(accU2[i][0]),
                                   lo_of(accU2[i][1]), hi_of(accU2[i][1]));
    }
}

// ---------------- K2: chunk-level state scan (elementwise parallel) ------------
__global__ __launch_bounds__(256)
void chunk_scan(const float* __restrict__ U, const float* __restrict__ G,
                const float* __restrict__ state0,
                float* __restrict__ Sc, float* __restrict__ stateOut){
    __shared__ float gs[NCH];
    const int bh = blockIdx.x;
    const int e  = blockIdx.y * 256 + threadIdx.x;   // 0..4095
    if (threadIdx.x < NCH) gs[threadIdx.x] = G[bh * NCH + threadIdx.x];
    __syncthreads();
    const size_t bs = (size_t)bh * 4096 + e;
    float S = state0[bs];
    float u = U[(size_t)bh * NCH * 4096 + e];
    #pragma unroll 4
    for (int c = 0; c < NCH; c++){
        const size_t uc = ((size_t)(bh * NCH + c)) * 4096 + e;
        float u_next = (c + 1 < NCH) ? U[uc + 4096] : 0.f;
        Sc[uc] = S;
        S = fmaf(gs[c], S, u);
        u = u_next;
    }
    stateOut[bs] = S;
}

// ---------------- K3: Y += diag(g) Q S^T ; emit fp16 hi/lo split of Y ----------
__global__ __launch_bounds__(256)
void chunk_inter(const float* __restrict__ Q, const float* __restrict__ Sc,
                 const float* __restrict__ gt, const float* __restrict__ Y,
                 hf* __restrict__ Yh, hf* __restrict__ Yl){
    __shared__ float Qs[64*TP];
    __shared__ float Ss[64*TP];
    __shared__ float sg[64];
    const int c  = blockIdx.x;
    const int bh = blockIdx.y;
    const int b  = bh >> 4, h = bh & 15;
    const int tid = threadIdx.x;
    const size_t base = ((size_t)(b * Tsz + c * CH) * Hh + h) * Dd;
    {
        const int r = tid >> 2, quad = tid & 3;
        const size_t off = base + (size_t)r * INNERx + quad * 16;
        const size_t soff = ((size_t)(bh * NCH + c)) * 4096 + r * 64 + quad * 16;
        #pragma unroll
        for (int l = 0; l < 16; l += 4){
            float4 qv = *(const float4*)(Q + off + l);
            float4 sv = *(const float4*)(Sc + soff + l);
            float* qr = Qs + r * TP + quad * 16 + l;
            float* sr = Ss + r * TP + quad * 16 + l;
            qr[0]=qv.x; qr[1]=qv.y; qr[2]=qv.z; qr[3]=qv.w;
            sr[0]=sv.x; sr[1]=sv.y; sr[2]=sv.z; sr[3]=sv.w;
        }
    }
    if (tid < 64) sg[tid] = gt[(size_t)bh * Tsz + c * CH + tid];
    __syncthreads();
    const int lane = tid & 31, w = tid >> 5;
    const int tr  = (((w & 3) << 2) | (lane & 3)) << 2;
    const int tci = (((w >> 2) << 3) | (lane >> 2)) << 2;
    ull acc2[4][4];
    #pragma unroll
    for (int i=0;i<4;i++)
        #pragma unroll
        for (int k=0;k<4;k++) acc2[i][k] = 0ull;
    #pragma unroll 8
    for (int j = 0; j < Dd; j += 2){
        ull qf2[4], sf2[4];
        #pragma unroll
        for (int i=0;i<4;i++) qf2[i] = *(const ull*)&Qs[(tr+i)*TP + j];
        #pragma unroll
        for (int k=0;k<4;k++) sf2[k] = *(const ull*)&Ss[(tci+k)*TP + j];
        #pragma unroll
        for (int i=0;i<4;i++)
            #pragma unroll
            for (int k=0;k<4;k++) ffma2(acc2[i][k], qf2[i], sf2[k]);
    }
    #pragma unroll
    for (int i=0;i<4;i++){
        float gt_ = sg[tr + i];
        const size_t off = base + (size_t)(tr + i) * INNERx + tci;
        float4 old = *(const float4*)(Y + off);
        float f0 = fmaf(gt_, lo_of(acc2[i][0]) + hi_of(acc2[i][0]), old.x);
        float f1 = fmaf(gt_, lo_of(acc2[i][1]) + hi_of(acc2[i][1]), old.y);
        float f2 = fmaf(gt_, lo_of(acc2[i][2]) + hi_of(acc2[i][2]), old.z);
        float f3 = fmaf(gt_, lo_of(acc2[i][3]) + hi_of(acc2[i][3]), old.w);
        hf h0 = __float2half(f0), h1 = __float2half(f1);
        hf h2 = __float2half(f2), h3 = __float2half(f3);
        hf l0 = __float2half(f0 - __half2float(h0));
        hf l1 = __float2half(f1 - __half2float(h1));
        hf l2 = __float2half(f2 - __half2float(h2));
        hf l3 = __float2half(f3 - __half2float(h3));
        __half2* hp = (__half2*)(Yh + off);
        __half2* lp = (__half2*)(Yl + off);
        hp[0] = __half2{h0, h1}; hp[1] = __half2{h2, h3};
        lp[0] = __half2{l0, l1}; lp[1] = __half2{l2, l3};
    }
}

// ---------------- launcher -----------------------------------------------------
extern "C" void kernel_launch(void* const* d_in, const int* in_sizes, int n_in,
                              void* d_out, int out_size){
    const float* x     = (const float*)d_in[0];
    const float* state = (const float*)d_in[1];
    const float* Wq    = (const float*)d_in[2];
    const float* Wk    = (const float*)d_in[3];
    const float* Wv    = (const float*)d_in[4];
    const float* Wa    = (const float*)d_in[5];
    const float* ba    = (const float*)d_in[6];
    const float* Wb    = (const float*)d_in[7];
    const float* bb    = (const float*)d_in[8];
    const float* Wo    = (const float*)d_in[9];

    float* out      = (float*)d_out;
    float* stateOut = out + (size_t)ROWS * DMx;

    float *Q, *K, *V, *Y, *al, *be, *U, *Sc, *G, *gt;
    hf *xh, *xl, *yh, *yl;
    cudaGetSymbolAddress((void**)&Q,  g_Q);
    cudaGetSymbolAddress((void**)&K,  g_K);
    cudaGetSymbolAddress((void**)&V,  g_V);
    cudaGetSymbolAddress((void**)&Y,  g_Y);
    cudaGetSymbolAddress((void**)&al, g_alpha);
    cudaGetSymbolAddress((void**)&be, g_beta);
    cudaGetSymbolAddress((void**)&U,  g_U);
    cudaGetSymbolAddress((void**)&Sc, g_Sc);
    cudaGetSymbolAddress((void**)&G,  g_G);
    cudaGetSymbolAddress((void**)&gt, g_gt);
    cudaGetSymbolAddress((void**)&xh, g_xh);
    cudaGetSymbolAddress((void**)&xl, g_xl);
    cudaGetSymbolAddress((void**)&yh, g_yh);
    cudaGetSymbolAddress((void**)&yl, g_yl);

    cudaFuncSetAttribute(gemm_qkv,    cudaFuncAttributeMaxDynamicSharedMemorySize, GEMM_SMEM);
    cudaFuncSetAttribute(gemm_out,    cudaFuncAttributeMaxDynamicSharedMemorySize, GEMM_SMEM);
    cudaFuncSetAttribute(chunk_intra, cudaFuncAttributeMaxDynamicSharedMemorySize, INTRA_SMEM);

    prep_kernel<<<8192 + 4096, 256>>>(x, Wq, Wk, Wv, Wo);
    ab_kernel<<<ROWS / 32, 256>>>(x, Wa, ba, Wb, bb, al, be);
    gemm_qkv<<<dim3(24, ROWS / 128), 256, GEMM_SMEM>>>(xh, xl, Q, K, V);
    chunk_intra<<<dim3(NCH, BH), 256, INTRA_SMEM>>>(Q, K, V, al, be, Y, U, G, gt);
    chunk_scan<<<dim3(BH, 16), 256>>>(U, G, state, Sc, stateOut);
    chunk_inter<<<dim3(NCH, BH), 256>>>(Q, Sc, gt, Y, yh, yl);
    gemm_out<<<dim3(DMx / 128, ROWS / 128), 256, GEMM_SMEM>>>(yh, yl, out);
}